// round 9
// baseline (speedup 1.0000x reference)
#include <cuda_runtime.h>
#include <cuda_bf16.h>
#include <cstdint>

// Problem constants
#define BB 4
#define SS 2048
#define EE 1024
#define HH 16
#define HD 64
#define E3 (3 * EE)

// Scratch (alloc-free requirement -> __device__ globals)
__device__ float g_qkv[BB * SS * E3];            // [b, s, 3E]  (~100 MB)
__device__ float g_attn[BB * SS * EE];           // [b, s, E]   (~33 MB)
// Pre-split K/V in bf16 hi/lo, mma-friendly layouts (u32 = bf16 pair)
__device__ uint32_t g_Khi[BB * HH * SS * 32];    // [bh][s][hdpair]
__device__ uint32_t g_Klo[BB * HH * SS * 32];
__device__ uint32_t g_Vhi[BB * HH * HD * (SS/2)];// [bh][hd][keypair]
__device__ uint32_t g_Vlo[BB * HH * HD * (SS/2)];

// ---------------------------------------------------------------------------
// helpers
// ---------------------------------------------------------------------------
__device__ __forceinline__ float f2tf32(float x) {
    uint32_t u;
    asm("cvt.rna.tf32.f32 %0, %1;" : "=r"(u) : "f"(x));
    return __uint_as_float(u);
}

__device__ __forceinline__ void mma_tf32(float* d, const uint32_t* a, const uint32_t* b) {
    asm volatile(
        "mma.sync.aligned.m16n8k8.row.col.f32.tf32.tf32.f32 "
        "{%0,%1,%2,%3}, {%4,%5,%6,%7}, {%8,%9}, {%0,%1,%2,%3};\n"
        : "+f"(d[0]), "+f"(d[1]), "+f"(d[2]), "+f"(d[3])
        : "r"(a[0]), "r"(a[1]), "r"(a[2]), "r"(a[3]), "r"(b[0]), "r"(b[1]));
}

__device__ __forceinline__ void mma_bf16(float* d, const uint32_t* a,
                                         uint32_t b0, uint32_t b1) {
    asm volatile(
        "mma.sync.aligned.m16n8k16.row.col.f32.bf16.bf16.f32 "
        "{%0,%1,%2,%3}, {%4,%5,%6,%7}, {%8,%9}, {%0,%1,%2,%3};\n"
        : "+f"(d[0]), "+f"(d[1]), "+f"(d[2]), "+f"(d[3])
        : "r"(a[0]), "r"(a[1]), "r"(a[2]), "r"(a[3]), "r"(b0), "r"(b1));
}

__device__ __forceinline__ void bsplit2(float x, float y, uint32_t& hi, uint32_t& lo) {
    __nv_bfloat162 H = __floats2bfloat162_rn(x, y);
    float rx = x - __bfloat162float(H.x);
    float ry = y - __bfloat162float(H.y);
    __nv_bfloat162 L = __floats2bfloat162_rn(rx, ry);
    hi = *reinterpret_cast<uint32_t*>(&H);
    lo = *reinterpret_cast<uint32_t*>(&L);
}

__device__ __forceinline__ float ex2(float x) {
    float r;
    asm("ex2.approx.ftz.f32 %0, %1;" : "=f"(r) : "f"(x));
    return r;
}

// ---------------------------------------------------------------------------
// tf32 GEMM, CTA tile 128x256, BK=16, warp tile 64x64 (8 warps = 2x4).
// Pad-free XOR-swizzled smem (fits 48KB static with double buffering):
//   As[r][k ^ (((r>>1)&3)<<2)], stride 16 -> ldmatrix conflict-free
//   Bs[r][c ^ ((r&3)<<3)],      stride 256 -> B frag conflict-free
// ---------------------------------------------------------------------------
#define GBM 128
#define GBN 256
#define GBK 16

__device__ __forceinline__ int aswz(int r, int k) { return k ^ (((r >> 1) & 3) << 2); }
__device__ __forceinline__ int bswz(int r, int c) { return c ^ ((r & 3) << 3); }

template <bool A_SCRATCH_ATTN, bool C_SCRATCH_QKV>
__global__ __launch_bounds__(256, 1)
void gemm_tf32(int M, int N, int K,
               const float* __restrict__ Ain,
               const float* __restrict__ B,
               const float* __restrict__ bias,
               float* __restrict__ Cout) {
    const float* A = A_SCRATCH_ATTN ? g_attn : Ain;
    float* C = C_SCRATCH_QKV ? g_qkv : Cout;

    __shared__ float As[2][GBM * GBK];    // 16 KB
    __shared__ float Bs[2][GBK * GBN];    // 32 KB

    const int tid  = threadIdx.x;
    const int warp = tid >> 5;
    const int lane = tid & 31;
    const int g    = lane >> 2;
    const int t4   = lane & 3;
    const int warpM = warp >> 2;        // 0..1  (* 64)
    const int warpN = warp & 3;         // 0..3  (* 64)
    const int blkM = blockIdx.y * GBM;
    const int blkN = blockIdx.x * GBN;

    const int rA = tid >> 1;            // 0..127
    const int cA = (tid & 1) * 8;       // 0 or 8
    const int rB = tid >> 4;            // 0..15
    const int cB = (tid & 15) * 16;     // 0..240

    const int nt = K / GBK;

    float4 a4[2], b4[4];

    auto fetch_tile = [&](int bk) {
        const int off = bk * GBK;
        a4[0] = *(const float4*)&A[(size_t)(blkM + rA) * K + off + cA];
        a4[1] = *(const float4*)&A[(size_t)(blkM + rA) * K + off + cA + 4];
#pragma unroll
        for (int j = 0; j < 4; ++j)
            b4[j] = *(const float4*)&B[(size_t)(off + rB) * N + blkN + cB + 4 * j];
    };
    auto store_tile = [&](int buf) {
        float* as = As[buf];
        float* bs = Bs[buf];
#pragma unroll
        for (int hh = 0; hh < 2; ++hh) {
            float4 t;
            t.x = f2tf32(a4[hh].x); t.y = f2tf32(a4[hh].y);
            t.z = f2tf32(a4[hh].z); t.w = f2tf32(a4[hh].w);
            *(float4*)&as[rA * GBK + aswz(rA, cA + 4 * hh)] = t;
        }
#pragma unroll
        for (int j = 0; j < 4; ++j) {
            float4 u;
            u.x = f2tf32(b4[j].x); u.y = f2tf32(b4[j].y);
            u.z = f2tf32(b4[j].z); u.w = f2tf32(b4[j].w);
            *(float4*)&bs[rB * GBN + bswz(rB, cB + 4 * j)] = u;
        }
    };

    fetch_tile(0);
    store_tile(0);
    __syncthreads();

    float acc[4][8][4];
#pragma unroll
    for (int mi = 0; mi < 4; ++mi)
#pragma unroll
        for (int ni = 0; ni < 8; ++ni)
#pragma unroll
            for (int j = 0; j < 4; ++j) acc[mi][ni][j] = 0.f;

    const int lm_row = lane & 15;
    const int lm_kof = (lane >> 4) << 2;

    for (int bk = 0; bk < nt; ++bk) {
        const int cur = bk & 1;
        if (bk + 1 < nt) fetch_tile(bk + 1);
        const float* as = As[cur];
        const float* bs = Bs[cur];
#pragma unroll
        for (int ks = 0; ks < GBK; ks += 8) {
            uint32_t bfrag[8][2];
#pragma unroll
            for (int ni = 0; ni < 8; ++ni) {
                int n0 = warpN * 64 + ni * 8 + g;
                bfrag[ni][0] = __float_as_uint(bs[(ks + t4) * GBN + bswz(ks + t4, n0)]);
                bfrag[ni][1] = __float_as_uint(bs[(ks + t4 + 4) * GBN + bswz(ks + t4 + 4, n0)]);
            }
#pragma unroll
            for (int mi = 0; mi < 4; ++mi) {
                const int m0 = warpM * 64 + mi * 16;
                const int row = m0 + lm_row;
                uint32_t af[4];
                uint32_t addr = (uint32_t)__cvta_generic_to_shared(
                    &as[row * GBK + aswz(row, ks + lm_kof)]);
                asm volatile(
                    "ldmatrix.sync.aligned.m8n8.x4.shared.b16 {%0,%1,%2,%3}, [%4];"
                    : "=r"(af[0]), "=r"(af[1]), "=r"(af[2]), "=r"(af[3])
                    : "r"(addr));
#pragma unroll
                for (int ni = 0; ni < 8; ++ni)
                    mma_tf32(acc[mi][ni], af, bfrag[ni]);
            }
        }
        if (bk + 1 < nt) store_tile(cur ^ 1);
        __syncthreads();
    }

    // epilogue: bias + store
#pragma unroll
    for (int mi = 0; mi < 4; ++mi) {
#pragma unroll
        for (int ni = 0; ni < 8; ++ni) {
            int row0 = blkM + warpM * 64 + mi * 16 + g;
            int col  = blkN + warpN * 64 + ni * 8 + 2 * t4;
            float2 b2 = *reinterpret_cast<const float2*>(&bias[col]);
            float2 r0, r1;
            r0.x = acc[mi][ni][0] + b2.x;
            r0.y = acc[mi][ni][1] + b2.y;
            r1.x = acc[mi][ni][2] + b2.x;
            r1.y = acc[mi][ni][3] + b2.y;
            *reinterpret_cast<float2*>(&C[(size_t)row0 * N + col]) = r0;
            *reinterpret_cast<float2*>(&C[(size_t)(row0 + 8) * N + col]) = r1;
        }
    }
}

// ---------------------------------------------------------------------------
// split_kv: one-time bf16 hi/lo split of K and V from g_qkv into dense
// mma-friendly layouts. Grid (SS/64, HH, BB), 128 threads.
// ---------------------------------------------------------------------------
__global__ __launch_bounds__(128)
void split_kv() {
    const int s0 = blockIdx.x * 64;
    const int h = blockIdx.y, b = blockIdx.z;
    const int bh = b * HH + h;
    const int tid = threadIdx.x;

    const size_t bbase = (size_t)b * SS * E3;
    const float* Kg = g_qkv + bbase + EE + (size_t)h * HD;
    const float* Vg = g_qkv + bbase + 2 * EE + (size_t)h * HD;

#pragma unroll
    for (int it = 0; it < 8; ++it) {
        int flat = it * 128 + tid;
        int key = flat >> 4, hd4 = flat & 15;
        float4 kx = *(const float4*)(Kg + (size_t)(s0 + key) * E3 + hd4 * 4);
        uint32_t h0, L0, h1, L1;
        bsplit2(kx.x, kx.y, h0, L0);
        bsplit2(kx.z, kx.w, h1, L1);
        size_t o = ((size_t)bh * SS + s0 + key) * 32 + 2 * hd4;
        g_Khi[o] = h0; g_Khi[o + 1] = h1;
        g_Klo[o] = L0; g_Klo[o + 1] = L1;
    }
#pragma unroll
    for (int it = 0; it < 4; ++it) {
        int flat = it * 128 + tid;
        int kp = flat & 31, hd4 = flat >> 5;
        const float* va = Vg + (size_t)(s0 + 2 * kp) * E3 + hd4 * 4;
        float4 A4 = *(const float4*)va;
        float4 B4 = *(const float4*)(va + E3);
        uint32_t hh, ll;
        size_t rb = ((size_t)bh * HD + 4 * hd4) * (SS / 2) + s0 / 2 + kp;
        bsplit2(A4.x, B4.x, hh, ll);
        g_Vhi[rb] = hh; g_Vlo[rb] = ll;
        bsplit2(A4.y, B4.y, hh, ll);
        g_Vhi[rb + (SS / 2)] = hh; g_Vlo[rb + (SS / 2)] = ll;
        bsplit2(A4.z, B4.z, hh, ll);
        g_Vhi[rb + 2 * (SS / 2)] = hh; g_Vlo[rb + 2 * (SS / 2)] = ll;
        bsplit2(A4.w, B4.w, hh, ll);
        g_Vhi[rb + 3 * (SS / 2)] = hh; g_Vlo[rb + 3 * (SS / 2)] = ll;
    }
}

// ---------------------------------------------------------------------------
// Tensor-core flash attention, bf16x3; K/V tiles copied from presplit scratch.
// Block 128 threads = 4 warps; 64 q-rows/block, 64-key tiles; stride 36.
// ---------------------------------------------------------------------------
#define AST 36

__global__ __launch_bounds__(128)
void flash_attn_mma(const int* __restrict__ amask) {
    __shared__ uint32_t KPhi[64 * AST];
    __shared__ uint32_t KPlo[64 * AST];
    __shared__ uint32_t VPhi[64 * AST];
    __shared__ uint32_t VPlo[64 * AST];
    __shared__ int Ms[64];

    const int qb = (int)(gridDim.x - 1 - blockIdx.x);   // heavy blocks first
    const int h = blockIdx.y, b = blockIdx.z;
    const int bh = b * HH + h;
    const int tid = threadIdx.x;
    const int warp = tid >> 5, lane = tid & 31;
    const int g = lane >> 2, t4 = lane & 3;

    const size_t bbase = (size_t)b * SS * E3;
    const float* Qg = g_qkv + bbase + (size_t)h * HD;

    const int qrow0 = qb * 64 + warp * 16;
    const int r0 = qrow0 + g;
    const int r1 = r0 + 8;

    const float qsc = 0.125f * 1.4426950408889634f;
    uint32_t Qhi[4][4], Qlo[4][4];
#pragma unroll
    for (int kf = 0; kf < 4; ++kf) {
        int hd0 = kf * 16 + 2 * t4;
        float2 x0 = *(const float2*)(Qg + (size_t)r0 * E3 + hd0);
        float2 x1 = *(const float2*)(Qg + (size_t)r1 * E3 + hd0);
        float2 x2 = *(const float2*)(Qg + (size_t)r0 * E3 + hd0 + 8);
        float2 x3 = *(const float2*)(Qg + (size_t)r1 * E3 + hd0 + 8);
        bsplit2(x0.x * qsc, x0.y * qsc, Qhi[kf][0], Qlo[kf][0]);
        bsplit2(x1.x * qsc, x1.y * qsc, Qhi[kf][1], Qlo[kf][1]);
        bsplit2(x2.x * qsc, x2.y * qsc, Qhi[kf][2], Qlo[kf][2]);
        bsplit2(x3.x * qsc, x3.y * qsc, Qhi[kf][3], Qlo[kf][3]);
    }

    float O[8][4];
#pragma unroll
    for (int nh = 0; nh < 8; ++nh)
#pragma unroll
        for (int j = 0; j < 4; ++j) O[nh][j] = 0.f;
    float m0 = -1e30f, m1 = -1e30f, l0 = 0.f, l1 = 0.f;

    const uint32_t* Khi = g_Khi + (size_t)bh * SS * 32;
    const uint32_t* Klo = g_Klo + (size_t)bh * SS * 32;
    const uint32_t* Vhi = g_Vhi + (size_t)bh * HD * (SS / 2);
    const uint32_t* Vlo = g_Vlo + (size_t)bh * HD * (SS / 2);

    for (int kt = 0; kt <= qb; ++kt) {
        const int k0 = kt * 64;

        // ---- dense tile copies from presplit scratch ----
#pragma unroll
        for (int it = 0; it < 4; ++it) {
            int idx = it * 128 + tid;          // 0..511
            int row = idx >> 3;                // 0..63
            int c4 = (idx & 7) * 4;            // 0..28
            *(uint4*)&KPhi[row * AST + c4] =
                *(const uint4*)&Khi[(size_t)(k0 + row) * 32 + c4];
            *(uint4*)&KPlo[row * AST + c4] =
                *(const uint4*)&Klo[(size_t)(k0 + row) * 32 + c4];
            *(uint4*)&VPhi[row * AST + c4] =
                *(const uint4*)&Vhi[(size_t)row * (SS / 2) + k0 / 2 + c4];
            *(uint4*)&VPlo[row * AST + c4] =
                *(const uint4*)&Vlo[(size_t)row * (SS / 2) + k0 / 2 + c4];
        }
        if (tid < 64) Ms[tid] = amask[b * SS + k0 + tid];
        __syncthreads();

        // ---- S = Q K^T (bf16x3) ----
        float S[8][4];
#pragma unroll
        for (int nf = 0; nf < 8; ++nf)
#pragma unroll
            for (int j = 0; j < 4; ++j) S[nf][j] = 0.f;

#pragma unroll
        for (int nf = 0; nf < 8; ++nf) {
            const uint32_t* kh = &KPhi[(8 * nf + g) * AST];
            const uint32_t* kl = &KPlo[(8 * nf + g) * AST];
#pragma unroll
            for (int kf = 0; kf < 4; ++kf) {
                uint32_t b0h = kh[8 * kf + t4], b1h = kh[8 * kf + t4 + 4];
                uint32_t b0l = kl[8 * kf + t4], b1l = kl[8 * kf + t4 + 4];
                mma_bf16(S[nf], Qhi[kf], b0h, b1h);
                mma_bf16(S[nf], Qhi[kf], b0l, b1l);
                mma_bf16(S[nf], Qlo[kf], b0h, b1h);
            }
        }

        const bool diag = (kt == qb);
#pragma unroll
        for (int nf = 0; nf < 8; ++nf) {
            int cl = 8 * nf + 2 * t4;
            int col = k0 + cl;
            bool mv0 = Ms[cl] != 0;
            bool mv1 = Ms[cl + 1] != 0;
            if (!(mv0 && (!diag || col     <= r0))) S[nf][0] = -1e30f;
            if (!(mv1 && (!diag || col + 1 <= r0))) S[nf][1] = -1e30f;
            if (!(mv0 && (!diag || col     <= r1))) S[nf][2] = -1e30f;
            if (!(mv1 && (!diag || col + 1 <= r1))) S[nf][3] = -1e30f;
        }

        float mx0 = -1e30f, mx1 = -1e30f;
#pragma unroll
        for (int nf = 0; nf < 8; ++nf) {
            mx0 = fmaxf(mx0, fmaxf(S[nf][0], S[nf][1]));
            mx1 = fmaxf(mx1, fmaxf(S[nf][2], S[nf][3]));
        }
        mx0 = fmaxf(mx0, __shfl_xor_sync(0xFFFFFFFFu, mx0, 1));
        mx0 = fmaxf(mx0, __shfl_xor_sync(0xFFFFFFFFu, mx0, 2));
        mx1 = fmaxf(mx1, __shfl_xor_sync(0xFFFFFFFFu, mx1, 1));
        mx1 = fmaxf(mx1, __shfl_xor_sync(0xFFFFFFFFu, mx1, 2));
        float mn0 = fmaxf(fmaxf(m0, mx0), -8e29f);
        float mn1 = fmaxf(fmaxf(m1, mx1), -8e29f);
        float al0 = ex2(m0 - mn0);
        float al1 = ex2(m1 - mn1);
        float s0 = 0.f, s1 = 0.f;
#pragma unroll
        for (int nf = 0; nf < 8; ++nf) {
            S[nf][0] = ex2(S[nf][0] - mn0); s0 += S[nf][0];
            S[nf][1] = ex2(S[nf][1] - mn0); s0 += S[nf][1];
            S[nf][2] = ex2(S[nf][2] - mn1); s1 += S[nf][2];
            S[nf][3] = ex2(S[nf][3] - mn1); s1 += S[nf][3];
        }
        s0 += __shfl_xor_sync(0xFFFFFFFFu, s0, 1);
        s0 += __shfl_xor_sync(0xFFFFFFFFu, s0, 2);
        s1 += __shfl_xor_sync(0xFFFFFFFFu, s1, 1);
        s1 += __shfl_xor_sync(0xFFFFFFFFu, s1, 2);
        l0 = l0 * al0 + s0;
        l1 = l1 * al1 + s1;
        m0 = mn0; m1 = mn1;
#pragma unroll
        for (int nh = 0; nh < 8; ++nh) {
            O[nh][0] *= al0; O[nh][1] *= al0;
            O[nh][2] *= al1; O[nh][3] *= al1;
        }

#pragma unroll
        for (int kf = 0; kf < 4; ++kf) {
            uint32_t ah[4], al[4];
            bsplit2(S[2 * kf][0],     S[2 * kf][1],     ah[0], al[0]);
            bsplit2(S[2 * kf][2],     S[2 * kf][3],     ah[1], al[1]);
            bsplit2(S[2 * kf + 1][0], S[2 * kf + 1][1], ah[2], al[2]);
            bsplit2(S[2 * kf + 1][2], S[2 * kf + 1][3], ah[3], al[3]);
#pragma unroll
            for (int nh = 0; nh < 8; ++nh) {
                const uint32_t* vh = &VPhi[(8 * nh + g) * AST];
                const uint32_t* vl = &VPlo[(8 * nh + g) * AST];
                uint32_t b0h = vh[8 * kf + t4], b1h = vh[8 * kf + t4 + 4];
                uint32_t b0l = vl[8 * kf + t4], b1l = vl[8 * kf + t4 + 4];
                mma_bf16(O[nh], ah, b0h, b1h);
                mma_bf16(O[nh], ah, b0l, b1l);
                mma_bf16(O[nh], al, b0h, b1h);
            }
        }
        __syncthreads();
    }

    const float inv0 = 1.0f / l0;
    const float inv1 = 1.0f / l1;
    float* outp = g_attn + (size_t)b * SS * EE + (size_t)h * HD;
#pragma unroll
    for (int nh = 0; nh < 8; ++nh) {
        int col = 8 * nh + 2 * t4;
        float2 w0, w1;
        w0.x = O[nh][0] * inv0; w0.y = O[nh][1] * inv0;
        w1.x = O[nh][2] * inv1; w1.y = O[nh][3] * inv1;
        *(float2*)(outp + (size_t)r0 * EE + col) = w0;
        *(float2*)(outp + (size_t)r1 * EE + col) = w1;
    }
}

// ---------------------------------------------------------------------------
// Launch — ONLY kernel launches
// ---------------------------------------------------------------------------
extern "C" void kernel_launch(void* const* d_in, const int* in_sizes, int n_in,
                              void* d_out, int out_size) {
    const float* x      = (const float*)d_in[0];
    const int*   amask  = (const int*)d_in[1];
    const float* W_attn = (const float*)d_in[2];
    const float* b_attn = (const float*)d_in[3];
    const float* W_proj = (const float*)d_in[4];
    const float* b_proj = (const float*)d_in[5];
    float* out = (float*)d_out;

    // 1) QKV projection: [8192,1024] @ [1024,3072] + bias -> g_qkv
    {
        dim3 grid(E3 / GBN, (BB * SS) / GBM);
        gemm_tf32<false, true><<<grid, 256>>>(BB * SS, E3, EE, x, W_attn, b_attn, nullptr);
    }
    // 2) Pre-split K/V into bf16 hi/lo scratch
    {
        dim3 grid(SS / 64, HH, BB);
        split_kv<<<grid, 128>>>();
    }
    // 3) Attention: g_qkv (+split scratch) -> g_attn
    {
        dim3 grid(SS / 64, HH, BB);
        flash_attn_mma<<<grid, 128>>>(amask);
    }
    // 4) Output projection: [8192,1024] @ [1024,1024] + bias -> d_out
    {
        dim3 grid(EE / GBN, (BB * SS) / GBM);
        gemm_tf32<true, false><<<grid, 256>>>(BB * SS, EE, EE, nullptr, W_proj, b_proj, out);
    }
}

// round 10
// speedup vs baseline: 1.0892x; 1.0892x over previous
#include <cuda_runtime.h>
#include <cuda_bf16.h>
#include <cstdint>

// Problem constants
#define BB 4
#define SS 2048
#define EE 1024
#define HH 16
#define HD 64
#define E3 (3 * EE)

// Scratch (alloc-free requirement -> __device__ globals)
__device__ float g_qkv[BB * SS * E3];            // [b, s, 3E]  (~100 MB)
__device__ float g_attn[BB * SS * EE];           // [b, s, E]   (~33 MB)
// Pre-split K/V in bf16 hi/lo, mma-friendly layouts (u32 = bf16 pair)
__device__ uint32_t g_Khi[BB * HH * SS * 32];    // [bh][s][hdpair]
__device__ uint32_t g_Klo[BB * HH * SS * 32];
__device__ uint32_t g_Vhi[BB * HH * HD * (SS/2)];// [bh][hd][keypair]
__device__ uint32_t g_Vlo[BB * HH * HD * (SS/2)];

// ---------------------------------------------------------------------------
// helpers
// ---------------------------------------------------------------------------
__device__ __forceinline__ float f2tf32(float x) {
    uint32_t u;
    asm("cvt.rna.tf32.f32 %0, %1;" : "=r"(u) : "f"(x));
    return __uint_as_float(u);
}

__device__ __forceinline__ void mma_tf32(float* d, const uint32_t* a, const uint32_t* b) {
    asm volatile(
        "mma.sync.aligned.m16n8k8.row.col.f32.tf32.tf32.f32 "
        "{%0,%1,%2,%3}, {%4,%5,%6,%7}, {%8,%9}, {%0,%1,%2,%3};\n"
        : "+f"(d[0]), "+f"(d[1]), "+f"(d[2]), "+f"(d[3])
        : "r"(a[0]), "r"(a[1]), "r"(a[2]), "r"(a[3]), "r"(b[0]), "r"(b[1]));
}

__device__ __forceinline__ void mma_bf16(float* d, const uint32_t* a,
                                         uint32_t b0, uint32_t b1) {
    asm volatile(
        "mma.sync.aligned.m16n8k16.row.col.f32.bf16.bf16.f32 "
        "{%0,%1,%2,%3}, {%4,%5,%6,%7}, {%8,%9}, {%0,%1,%2,%3};\n"
        : "+f"(d[0]), "+f"(d[1]), "+f"(d[2]), "+f"(d[3])
        : "r"(a[0]), "r"(a[1]), "r"(a[2]), "r"(a[3]), "r"(b0), "r"(b1));
}

__device__ __forceinline__ void bsplit2(float x, float y, uint32_t& hi, uint32_t& lo) {
    __nv_bfloat162 H = __floats2bfloat162_rn(x, y);
    float rx = x - __bfloat162float(H.x);
    float ry = y - __bfloat162float(H.y);
    __nv_bfloat162 L = __floats2bfloat162_rn(rx, ry);
    hi = *reinterpret_cast<uint32_t*>(&H);
    lo = *reinterpret_cast<uint32_t*>(&L);
}

__device__ __forceinline__ float ex2(float x) {
    float r;
    asm("ex2.approx.ftz.f32 %0, %1;" : "=f"(r) : "f"(x));
    return r;
}

// ---------------------------------------------------------------------------
// tf32 GEMM — EXACT R6 configuration (measured: 2 CTAs/SM, tensor 48.5%).
// CTA tile 128x128, BK=16, warp tile 64x32 (8 warps = 2x4), double-buffered,
// ldmatrix A feed (stride 20), conflict-free B feed (stride 136).
// ---------------------------------------------------------------------------
#define GBM 128
#define GBN 128
#define GBK 16
#define ASTRIDE (GBK + 4)    // 20 floats
#define BSTRIDE (GBN + 8)    // 136 floats

template <bool A_SCRATCH_ATTN, bool C_SCRATCH_QKV>
__global__ __launch_bounds__(256, 2)
void gemm_tf32(int M, int N, int K,
               const float* __restrict__ Ain,
               const float* __restrict__ B,
               const float* __restrict__ bias,
               float* __restrict__ Cout) {
    const float* A = A_SCRATCH_ATTN ? g_attn : Ain;
    float* C = C_SCRATCH_QKV ? g_qkv : Cout;

    __shared__ float As[2][GBM * ASTRIDE];
    __shared__ float Bs[2][GBK * BSTRIDE];

    const int tid  = threadIdx.x;
    const int warp = tid >> 5;
    const int lane = tid & 31;
    const int g    = lane >> 2;
    const int t4   = lane & 3;
    const int warpM = warp >> 2;
    const int warpN = warp & 3;
    const int blkM = blockIdx.y * GBM;
    const int blkN = blockIdx.x * GBN;

    const int rA = tid >> 1;            // 0..127
    const int cA = (tid & 1) * 8;       // 0 or 8
    const int rB = tid >> 4;            // 0..15
    const int cB = (tid & 15) * 8;      // 0..120

    const int nt = K / GBK;

    float4 a4[2], b4[2];

    auto fetch_tile = [&](int bk) {
        const int off = bk * GBK;
        a4[0] = *(const float4*)&A[(size_t)(blkM + rA) * K + off + cA];
        a4[1] = *(const float4*)&A[(size_t)(blkM + rA) * K + off + cA + 4];
        b4[0] = *(const float4*)&B[(size_t)(off + rB) * N + blkN + cB];
        b4[1] = *(const float4*)&B[(size_t)(off + rB) * N + blkN + cB + 4];
    };
    auto store_tile = [&](int buf) {
        float* as = As[buf];
        float* bs = Bs[buf];
#pragma unroll
        for (int hh = 0; hh < 2; ++hh) {
            float4 t;
            t.x = f2tf32(a4[hh].x); t.y = f2tf32(a4[hh].y);
            t.z = f2tf32(a4[hh].z); t.w = f2tf32(a4[hh].w);
            *(float4*)&as[rA * ASTRIDE + cA + 4 * hh] = t;
            float4 u;
            u.x = f2tf32(b4[hh].x); u.y = f2tf32(b4[hh].y);
            u.z = f2tf32(b4[hh].z); u.w = f2tf32(b4[hh].w);
            *(float4*)&bs[rB * BSTRIDE + cB + 4 * hh] = u;
        }
    };

    fetch_tile(0);
    store_tile(0);
    __syncthreads();

    float acc[4][4][4];
#pragma unroll
    for (int mi = 0; mi < 4; ++mi)
#pragma unroll
        for (int ni = 0; ni < 4; ++ni)
#pragma unroll
            for (int j = 0; j < 4; ++j) acc[mi][ni][j] = 0.f;

    const int lm_row = lane & 15;
    const int lm_kof = (lane >> 4) << 2;

    for (int bk = 0; bk < nt; ++bk) {
        const int cur = bk & 1;
        if (bk + 1 < nt) fetch_tile(bk + 1);
        const float* as = As[cur];
        const float* bs = Bs[cur];
#pragma unroll
        for (int ks = 0; ks < GBK; ks += 8) {
            uint32_t bfrag[4][2];
#pragma unroll
            for (int ni = 0; ni < 4; ++ni) {
                int n0 = warpN * 32 + ni * 8 + g;
                bfrag[ni][0] = __float_as_uint(bs[(ks + t4) * BSTRIDE + n0]);
                bfrag[ni][1] = __float_as_uint(bs[(ks + t4 + 4) * BSTRIDE + n0]);
            }
#pragma unroll
            for (int mi = 0; mi < 4; ++mi) {
                const int m0 = warpM * 64 + mi * 16;
                uint32_t af[4];
                uint32_t addr = (uint32_t)__cvta_generic_to_shared(
                    &as[(m0 + lm_row) * ASTRIDE + ks + lm_kof]);
                asm volatile(
                    "ldmatrix.sync.aligned.m8n8.x4.shared.b16 {%0,%1,%2,%3}, [%4];"
                    : "=r"(af[0]), "=r"(af[1]), "=r"(af[2]), "=r"(af[3])
                    : "r"(addr));
#pragma unroll
                for (int ni = 0; ni < 4; ++ni)
                    mma_tf32(acc[mi][ni], af, bfrag[ni]);
            }
        }
        if (bk + 1 < nt) store_tile(cur ^ 1);
        __syncthreads();
    }

    // epilogue: bias + store
#pragma unroll
    for (int mi = 0; mi < 4; ++mi) {
#pragma unroll
        for (int ni = 0; ni < 4; ++ni) {
            int row0 = blkM + warpM * 64 + mi * 16 + g;
            int col  = blkN + warpN * 32 + ni * 8 + 2 * t4;
            float2 b2 = *reinterpret_cast<const float2*>(&bias[col]);
            float2 r0, r1;
            r0.x = acc[mi][ni][0] + b2.x;
            r0.y = acc[mi][ni][1] + b2.y;
            r1.x = acc[mi][ni][2] + b2.x;
            r1.y = acc[mi][ni][3] + b2.y;
            *reinterpret_cast<float2*>(&C[(size_t)row0 * N + col]) = r0;
            *reinterpret_cast<float2*>(&C[(size_t)(row0 + 8) * N + col]) = r1;
        }
    }
}

// ---------------------------------------------------------------------------
// split_kv: one-time bf16 hi/lo split of K and V from g_qkv into dense
// mma-friendly layouts. Grid (SS/64, HH, BB), 128 threads.
// ---------------------------------------------------------------------------
__global__ __launch_bounds__(128)
void split_kv() {
    const int s0 = blockIdx.x * 64;
    const int h = blockIdx.y, b = blockIdx.z;
    const int bh = b * HH + h;
    const int tid = threadIdx.x;

    const size_t bbase = (size_t)b * SS * E3;
    const float* Kg = g_qkv + bbase + EE + (size_t)h * HD;
    const float* Vg = g_qkv + bbase + 2 * EE + (size_t)h * HD;

#pragma unroll
    for (int it = 0; it < 8; ++it) {
        int flat = it * 128 + tid;
        int key = flat >> 4, hd4 = flat & 15;
        float4 kx = *(const float4*)(Kg + (size_t)(s0 + key) * E3 + hd4 * 4);
        uint32_t h0, L0, h1, L1;
        bsplit2(kx.x, kx.y, h0, L0);
        bsplit2(kx.z, kx.w, h1, L1);
        size_t o = ((size_t)bh * SS + s0 + key) * 32 + 2 * hd4;
        g_Khi[o] = h0; g_Khi[o + 1] = h1;
        g_Klo[o] = L0; g_Klo[o + 1] = L1;
    }
#pragma unroll
    for (int it = 0; it < 4; ++it) {
        int flat = it * 128 + tid;
        int kp = flat & 31, hd4 = flat >> 5;
        const float* va = Vg + (size_t)(s0 + 2 * kp) * E3 + hd4 * 4;
        float4 A4 = *(const float4*)va;
        float4 B4 = *(const float4*)(va + E3);
        uint32_t hh, ll;
        size_t rb = ((size_t)bh * HD + 4 * hd4) * (SS / 2) + s0 / 2 + kp;
        bsplit2(A4.x, B4.x, hh, ll);
        g_Vhi[rb] = hh; g_Vlo[rb] = ll;
        bsplit2(A4.y, B4.y, hh, ll);
        g_Vhi[rb + (SS / 2)] = hh; g_Vlo[rb + (SS / 2)] = ll;
        bsplit2(A4.z, B4.z, hh, ll);
        g_Vhi[rb + 2 * (SS / 2)] = hh; g_Vlo[rb + 2 * (SS / 2)] = ll;
        bsplit2(A4.w, B4.w, hh, ll);
        g_Vhi[rb + 3 * (SS / 2)] = hh; g_Vlo[rb + 3 * (SS / 2)] = ll;
    }
}

// ---------------------------------------------------------------------------
// Tensor-core flash attention, bf16x3; K/V tiles copied from presplit scratch.
// Block 128 threads = 4 warps; 64 q-rows/block, 64-key tiles; stride 36.
// ---------------------------------------------------------------------------
#define AST 36

__global__ __launch_bounds__(128)
void flash_attn_mma(const int* __restrict__ amask) {
    __shared__ uint32_t KPhi[64 * AST];
    __shared__ uint32_t KPlo[64 * AST];
    __shared__ uint32_t VPhi[64 * AST];
    __shared__ uint32_t VPlo[64 * AST];
    __shared__ int Ms[64];

    const int qb = (int)(gridDim.x - 1 - blockIdx.x);   // heavy blocks first
    const int h = blockIdx.y, b = blockIdx.z;
    const int bh = b * HH + h;
    const int tid = threadIdx.x;
    const int warp = tid >> 5, lane = tid & 31;
    const int g = lane >> 2, t4 = lane & 3;

    const size_t bbase = (size_t)b * SS * E3;
    const float* Qg = g_qkv + bbase + (size_t)h * HD;

    const int qrow0 = qb * 64 + warp * 16;
    const int r0 = qrow0 + g;
    const int r1 = r0 + 8;

    const float qsc = 0.125f * 1.4426950408889634f;
    uint32_t Qhi[4][4], Qlo[4][4];
#pragma unroll
    for (int kf = 0; kf < 4; ++kf) {
        int hd0 = kf * 16 + 2 * t4;
        float2 x0 = *(const float2*)(Qg + (size_t)r0 * E3 + hd0);
        float2 x1 = *(const float2*)(Qg + (size_t)r1 * E3 + hd0);
        float2 x2 = *(const float2*)(Qg + (size_t)r0 * E3 + hd0 + 8);
        float2 x3 = *(const float2*)(Qg + (size_t)r1 * E3 + hd0 + 8);
        bsplit2(x0.x * qsc, x0.y * qsc, Qhi[kf][0], Qlo[kf][0]);
        bsplit2(x1.x * qsc, x1.y * qsc, Qhi[kf][1], Qlo[kf][1]);
        bsplit2(x2.x * qsc, x2.y * qsc, Qhi[kf][2], Qlo[kf][2]);
        bsplit2(x3.x * qsc, x3.y * qsc, Qhi[kf][3], Qlo[kf][3]);
    }

    float O[8][4];
#pragma unroll
    for (int nh = 0; nh < 8; ++nh)
#pragma unroll
        for (int j = 0; j < 4; ++j) O[nh][j] = 0.f;
    float m0 = -1e30f, m1 = -1e30f, l0 = 0.f, l1 = 0.f;

    const uint32_t* Khi = g_Khi + (size_t)bh * SS * 32;
    const uint32_t* Klo = g_Klo + (size_t)bh * SS * 32;
    const uint32_t* Vhi = g_Vhi + (size_t)bh * HD * (SS / 2);
    const uint32_t* Vlo = g_Vlo + (size_t)bh * HD * (SS / 2);

    for (int kt = 0; kt <= qb; ++kt) {
        const int k0 = kt * 64;

        // ---- dense tile copies from presplit scratch ----
#pragma unroll
        for (int it = 0; it < 4; ++it) {
            int idx = it * 128 + tid;          // 0..511
            int row = idx >> 3;                // 0..63
            int c4 = (idx & 7) * 4;            // 0..28
            *(uint4*)&KPhi[row * AST + c4] =
                *(const uint4*)&Khi[(size_t)(k0 + row) * 32 + c4];
            *(uint4*)&KPlo[row * AST + c4] =
                *(const uint4*)&Klo[(size_t)(k0 + row) * 32 + c4];
            *(uint4*)&VPhi[row * AST + c4] =
                *(const uint4*)&Vhi[(size_t)row * (SS / 2) + k0 / 2 + c4];
            *(uint4*)&VPlo[row * AST + c4] =
                *(const uint4*)&Vlo[(size_t)row * (SS / 2) + k0 / 2 + c4];
        }
        if (tid < 64) Ms[tid] = amask[b * SS + k0 + tid];
        __syncthreads();

        // ---- S = Q K^T (bf16x3) ----
        float S[8][4];
#pragma unroll
        for (int nf = 0; nf < 8; ++nf)
#pragma unroll
            for (int j = 0; j < 4; ++j) S[nf][j] = 0.f;

#pragma unroll
        for (int nf = 0; nf < 8; ++nf) {
            const uint32_t* kh = &KPhi[(8 * nf + g) * AST];
            const uint32_t* kl = &KPlo[(8 * nf + g) * AST];
#pragma unroll
            for (int kf = 0; kf < 4; ++kf) {
                uint32_t b0h = kh[8 * kf + t4], b1h = kh[8 * kf + t4 + 4];
                uint32_t b0l = kl[8 * kf + t4], b1l = kl[8 * kf + t4 + 4];
                mma_bf16(S[nf], Qhi[kf], b0h, b1h);
                mma_bf16(S[nf], Qhi[kf], b0l, b1l);
                mma_bf16(S[nf], Qlo[kf], b0h, b1h);
            }
        }

        const bool diag = (kt == qb);
#pragma unroll
        for (int nf = 0; nf < 8; ++nf) {
            int cl = 8 * nf + 2 * t4;
            int col = k0 + cl;
            bool mv0 = Ms[cl] != 0;
            bool mv1 = Ms[cl + 1] != 0;
            if (!(mv0 && (!diag || col     <= r0))) S[nf][0] = -1e30f;
            if (!(mv1 && (!diag || col + 1 <= r0))) S[nf][1] = -1e30f;
            if (!(mv0 && (!diag || col     <= r1))) S[nf][2] = -1e30f;
            if (!(mv1 && (!diag || col + 1 <= r1))) S[nf][3] = -1e30f;
        }

        float mx0 = -1e30f, mx1 = -1e30f;
#pragma unroll
        for (int nf = 0; nf < 8; ++nf) {
            mx0 = fmaxf(mx0, fmaxf(S[nf][0], S[nf][1]));
            mx1 = fmaxf(mx1, fmaxf(S[nf][2], S[nf][3]));
        }
        mx0 = fmaxf(mx0, __shfl_xor_sync(0xFFFFFFFFu, mx0, 1));
        mx0 = fmaxf(mx0, __shfl_xor_sync(0xFFFFFFFFu, mx0, 2));
        mx1 = fmaxf(mx1, __shfl_xor_sync(0xFFFFFFFFu, mx1, 1));
        mx1 = fmaxf(mx1, __shfl_xor_sync(0xFFFFFFFFu, mx1, 2));
        float mn0 = fmaxf(fmaxf(m0, mx0), -8e29f);
        float mn1 = fmaxf(fmaxf(m1, mx1), -8e29f);
        float al0 = ex2(m0 - mn0);
        float al1 = ex2(m1 - mn1);
        float s0 = 0.f, s1 = 0.f;
#pragma unroll
        for (int nf = 0; nf < 8; ++nf) {
            S[nf][0] = ex2(S[nf][0] - mn0); s0 += S[nf][0];
            S[nf][1] = ex2(S[nf][1] - mn0); s0 += S[nf][1];
            S[nf][2] = ex2(S[nf][2] - mn1); s1 += S[nf][2];
            S[nf][3] = ex2(S[nf][3] - mn1); s1 += S[nf][3];
        }
        s0 += __shfl_xor_sync(0xFFFFFFFFu, s0, 1);
        s0 += __shfl_xor_sync(0xFFFFFFFFu, s0, 2);
        s1 += __shfl_xor_sync(0xFFFFFFFFu, s1, 1);
        s1 += __shfl_xor_sync(0xFFFFFFFFu, s1, 2);
        l0 = l0 * al0 + s0;
        l1 = l1 * al1 + s1;
        m0 = mn0; m1 = mn1;
#pragma unroll
        for (int nh = 0; nh < 8; ++nh) {
            O[nh][0] *= al0; O[nh][1] *= al0;
            O[nh][2] *= al1; O[nh][3] *= al1;
        }

#pragma unroll
        for (int kf = 0; kf < 4; ++kf) {
            uint32_t ah[4], al[4];
            bsplit2(S[2 * kf][0],     S[2 * kf][1],     ah[0], al[0]);
            bsplit2(S[2 * kf][2],     S[2 * kf][3],     ah[1], al[1]);
            bsplit2(S[2 * kf + 1][0], S[2 * kf + 1][1], ah[2], al[2]);
            bsplit2(S[2 * kf + 1][2], S[2 * kf + 1][3], ah[3], al[3]);
#pragma unroll
            for (int nh = 0; nh < 8; ++nh) {
                const uint32_t* vh = &VPhi[(8 * nh + g) * AST];
                const uint32_t* vl = &VPlo[(8 * nh + g) * AST];
                uint32_t b0h = vh[8 * kf + t4], b1h = vh[8 * kf + t4 + 4];
                uint32_t b0l = vl[8 * kf + t4], b1l = vl[8 * kf + t4 + 4];
                mma_bf16(O[nh], ah, b0h, b1h);
                mma_bf16(O[nh], ah, b0l, b1l);
                mma_bf16(O[nh], al, b0h, b1h);
            }
        }
        __syncthreads();
    }

    const float inv0 = 1.0f / l0;
    const float inv1 = 1.0f / l1;
    float* outp = g_attn + (size_t)b * SS * EE + (size_t)h * HD;
#pragma unroll
    for (int nh = 0; nh < 8; ++nh) {
        int col = 8 * nh + 2 * t4;
        float2 w0, w1;
        w0.x = O[nh][0] * inv0; w0.y = O[nh][1] * inv0;
        w1.x = O[nh][2] * inv1; w1.y = O[nh][3] * inv1;
        *(float2*)(outp + (size_t)r0 * EE + col) = w0;
        *(float2*)(outp + (size_t)r1 * EE + col) = w1;
    }
}

// ---------------------------------------------------------------------------
// Launch — ONLY kernel launches
// ---------------------------------------------------------------------------
extern "C" void kernel_launch(void* const* d_in, const int* in_sizes, int n_in,
                              void* d_out, int out_size) {
    const float* x      = (const float*)d_in[0];
    const int*   amask  = (const int*)d_in[1];
    const float* W_attn = (const float*)d_in[2];
    const float* b_attn = (const float*)d_in[3];
    const float* W_proj = (const float*)d_in[4];
    const float* b_proj = (const float*)d_in[5];
    float* out = (float*)d_out;

    // 1) QKV projection: [8192,1024] @ [1024,3072] + bias -> g_qkv
    {
        dim3 grid(E3 / GBN, (BB * SS) / GBM);
        gemm_tf32<false, true><<<grid, 256>>>(BB * SS, E3, EE, x, W_attn, b_attn, nullptr);
    }
    // 2) Pre-split K/V into bf16 hi/lo scratch
    {
        dim3 grid(SS / 64, HH, BB);
        split_kv<<<grid, 128>>>();
    }
    // 3) Attention: g_qkv (+split scratch) -> g_attn
    {
        dim3 grid(SS / 64, HH, BB);
        flash_attn_mma<<<grid, 128>>>(amask);
    }
    // 4) Output projection: [8192,1024] @ [1024,1024] + bias -> d_out
    {
        dim3 grid(EE / GBN, (BB * SS) / GBM);
        gemm_tf32<true, false><<<grid, 256>>>(BB * SS, EE, EE, nullptr, W_proj, b_proj, out);
    }
}